// round 1
// baseline (speedup 1.0000x reference)
#include <cuda_runtime.h>
#include <cuda_bf16.h>

#define HH 1024
#define WW 1024
#define NB 8

// Load 6 consecutive values (cols w0-1 .. w0+4) from row hh of a (HH,WW) plane,
// with zero padding outside. w0 is a multiple of 4, so [w0..w0+3] is a single
// aligned float4; only the two edge scalars need predication.
__device__ __forceinline__ void load_row6(const float* __restrict__ base, int hh,
                                          int w0, float out[6]) {
    if (hh < 0 || hh >= HH) {
#pragma unroll
        for (int c = 0; c < 6; c++) out[c] = 0.0f;
        return;
    }
    const float* row = base + (size_t)hh * WW;
    float4 v = *reinterpret_cast<const float4*>(row + w0);
    out[1] = v.x; out[2] = v.y; out[3] = v.z; out[4] = v.w;
    out[0] = (w0 > 0) ? row[w0 - 1] : 0.0f;
    out[5] = (w0 + 4 < WW) ? row[w0 + 4] : 0.0f;
}

__global__ void __launch_bounds__(128)
small_sm_block_kernel(const float* __restrict__ image,
                      const float* __restrict__ x,
                      const float* __restrict__ wgt,   // (9,1,3,3) = 81
                      const float* __restrict__ bias,  // (9,)
                      float* __restrict__ y) {
    __shared__ float sw[81];
    __shared__ float sb[9];
    int t = threadIdx.x;
    if (t < 81) sw[t] = wgt[t];
    if (t < 9)  sb[t] = bias[t];
    __syncthreads();

    const int h  = blockIdx.y;
    const int w0 = (blockIdx.x * blockDim.x + t) * 4;

    // ---- image neighborhood: rows h-1..h+1, cols w0-1..w0+4 ----
    float img[3][6];
#pragma unroll
    for (int r = 0; r < 3; r++) load_row6(image, h - 1 + r, w0, img[r]);

    // ---- K[j][p] = bias[j] + sum_{a,d} img[a][p+d] * w[j, a, d]  (correlation, SAME) ----
    float K[9][4];
#pragma unroll
    for (int j = 0; j < 9; j++) {
        const float bj = sb[j];
#pragma unroll
        for (int p = 0; p < 4; p++) K[j][p] = bj;
#pragma unroll
        for (int a = 0; a < 3; a++) {
#pragma unroll
            for (int d = 0; d < 3; d++) {
                const float wv = sw[j * 9 + a * 3 + d];
#pragma unroll
                for (int p = 0; p < 4; p++) K[j][p] += img[a][p + d] * wv;
            }
        }
    }

    // ---- apply: y[b,h,w0+p] = sum_{a,d} xpad[b,h-1+a,w0+p-1+d] * K[3a+d][p] ----
#pragma unroll
    for (int b = 0; b < NB; b++) {
        const float* xb = x + (size_t)b * HH * WW;
        float xr[3][6];
#pragma unroll
        for (int r = 0; r < 3; r++) load_row6(xb, h - 1 + r, w0, xr[r]);

        float acc[4] = {0.f, 0.f, 0.f, 0.f};
#pragma unroll
        for (int a = 0; a < 3; a++) {
#pragma unroll
            for (int d = 0; d < 3; d++) {
                const int j = a * 3 + d;
#pragma unroll
                for (int p = 0; p < 4; p++) acc[p] += xr[a][p + d] * K[j][p];
            }
        }

        float4 o;
        o.x = acc[0]; o.y = acc[1]; o.z = acc[2]; o.w = acc[3];
        *reinterpret_cast<float4*>(y + (size_t)b * HH * WW + (size_t)h * WW + w0) = o;
    }
}

extern "C" void kernel_launch(void* const* d_in, const int* in_sizes, int n_in,
                              void* d_out, int out_size) {
    const float* image = (const float*)d_in[0];  // (1, 1024, 1024)
    const float* x     = (const float*)d_in[1];  // (8, 1, 1024, 1024)
    const float* klw   = (const float*)d_in[2];  // (9, 1, 3, 3)
    const float* klb   = (const float*)d_in[3];  // (9,)
    float* y = (float*)d_out;                    // (8, 1, 1024, 1024)

    dim3 block(128);
    dim3 grid(WW / 4 / 128, HH);  // (2, 1024)
    small_sm_block_kernel<<<grid, block>>>(image, x, klw, klb, y);
}